// round 1
// baseline (speedup 1.0000x reference)
#include <cuda_runtime.h>

#define N_GROUPS 5
#define CIN 10
#define NPTS 32
#define COUT 64
#define NACC 65          // 55 upper-tri second-moment entries + 10 first moments
#define BN_EPS 1e-3f

// global scratch (no allocations allowed)
__device__ float g_acc[N_GROUPS * NACC];
__device__ int   g_cnt[N_GROUPS];
__device__ float g_scale[N_GROUPS * COUT];
__device__ float g_shift[N_GROUPS * COUT];

__device__ __forceinline__ int group_id(int num) {
    if (num < 2) return 0;
    if (num < 3) return 1;
    if (num < 4) return 2;
    if (num < 16) return 3;
    return 4;
}

__global__ void zero_kernel() {
    int t = threadIdx.x;
    if (t < N_GROUPS * NACC) g_acc[t] = 0.f;
    if (t < N_GROUPS) g_cnt[t] = 0;
}

// ---------------------------------------------------------------------------
// Pass 1: per-group input moments.  S[g][i] = sum in_i ; M[g][i<=j] = sum in_i*in_j
// block = 256 threads = 8 warps; each warp owns one voxel per iteration.
// Lane k accumulates entries k (a0) and k+32 (a1); lane 0 also entry 64 (a2).
// ---------------------------------------------------------------------------
__global__ void __launch_bounds__(256) stats_kernel(
    const float* __restrict__ in, const int* __restrict__ num, int N)
{
    __shared__ float sIn[8 * NPTS * CIN];        // 2560 floats staged coalesced
    __shared__ float sAcc[N_GROUPS * NACC];
    __shared__ int   sCnt[N_GROUPS];

    int tid = threadIdx.x;
    for (int k = tid; k < N_GROUPS * NACC; k += 256) sAcc[k] = 0.f;
    if (tid < N_GROUPS) sCnt[tid] = 0;

    int w = tid >> 5, lane = tid & 31;

    // entry -> (i,j) mapping for this lane (computed once)
    int i0, j0, i1, j1;
    {
        int e = lane, i = 0;
        while (e >= CIN - i) { e -= CIN - i; i++; }
        i0 = i; j0 = i + e;
    }
    {
        int e1 = lane + 32;
        if (e1 < 55) {
            int e = e1, i = 0;
            while (e >= CIN - i) { e -= CIN - i; i++; }
            i1 = i; j1 = i + e;
        } else {
            i1 = e1 - 55; j1 = -1;   // first-moment entry S[i1]
        }
    }
    __syncthreads();

    for (int n0 = blockIdx.x * 8; n0 < N; n0 += gridDim.x * 8) {
        int nv = min(8, N - n0);
        // stage nv voxels (contiguous) into smem, coalesced float4
        int nf4 = nv * (NPTS * CIN / 4);
        const float4* src = (const float4*)(in + (size_t)n0 * (NPTS * CIN));
        for (int k = tid; k < nf4; k += 256) ((float4*)sIn)[k] = src[k];
        __syncthreads();

        if (w < nv) {
            int n = n0 + w;
            int g = group_id(num[n]);
            const float* sv = sIn + w * (NPTS * CIN);
            float a0 = 0.f, a1 = 0.f, a2 = 0.f;
            #pragma unroll
            for (int p = 0; p < NPTS; p++) {
                const float* row = sv + p * CIN;
                a0 += row[i0] * row[j0];
                if (j1 >= 0) a1 += row[i1] * row[j1];
                else         a1 += row[i1];
                if (lane == 0) a2 += row[CIN - 1];   // entry 64 = S[9]
            }
            atomicAdd(&sAcc[g * NACC + lane], a0);
            atomicAdd(&sAcc[g * NACC + 32 + lane], a1);
            if (lane == 0) {
                atomicAdd(&sAcc[g * NACC + 64], a2);
                atomicAdd(&sCnt[g], 1);
            }
        }
        __syncthreads();
    }

    // flush block partials
    for (int k = tid; k < N_GROUPS * NACC; k += 256) atomicAdd(&g_acc[k], sAcc[k]);
    if (tid < N_GROUPS) atomicAdd(&g_cnt[tid], sCnt[tid]);
}

// ---------------------------------------------------------------------------
// Tiny finalize: per (g,c): mean = (S.w)/cnt ; E[x^2] = w^T M w / cnt
// scale = gamma * rsqrt(var+eps) ; shift = beta - mean*scale
// ---------------------------------------------------------------------------
__global__ void finalize_kernel(const float* __restrict__ W,
                                const float* __restrict__ gamma,
                                const float* __restrict__ beta)
{
    int t = threadIdx.x;
    if (t >= N_GROUPS * COUT) return;
    int g = t / COUT, c = t % COUT;
    float w[CIN];
    #pragma unroll
    for (int i = 0; i < CIN; i++) w[i] = W[(g * CIN + i) * COUT + c];

    const float* acc = &g_acc[g * NACC];
    float sum = 0.f;
    #pragma unroll
    for (int i = 0; i < CIN; i++) sum += acc[55 + i] * w[i];

    float sq = 0.f;
    int k = 0;
    #pragma unroll
    for (int i = 0; i < CIN; i++) {
        #pragma unroll 10
        for (int j = i; j < CIN; j++) {
            float term = acc[k++] * w[i] * w[j];
            sq += (i == j) ? term : 2.f * term;
        }
    }
    float denom = fmaxf((float)g_cnt[g] * (float)NPTS, 1.f);
    float mean = sum / denom;
    float var  = sq / denom - mean * mean;
    float scale = gamma[t] * rsqrtf(var + BN_EPS);
    g_scale[t] = scale;
    g_shift[t] = beta[t] - mean * scale;
}

// ---------------------------------------------------------------------------
// Pass 2: recompute x = in @ W[g], affine+relu, max over P, write [N,P,128].
// Persistent blocks; all 5 W matrices + scale/shift live in smem.
// thread -> (p = tid/8, 8 channels c0 = (tid&7)*8)
// ---------------------------------------------------------------------------
__global__ void __launch_bounds__(256) main_kernel(
    const float* __restrict__ in, const int* __restrict__ num,
    const float* __restrict__ W, float* __restrict__ out, int N)
{
    __shared__ float sW[N_GROUPS * CIN * COUT];   // 3200 floats
    __shared__ float sSc[N_GROUPS * COUT];
    __shared__ float sSh[N_GROUPS * COUT];
    __shared__ float sIn[NPTS * CIN];             // 320 floats
    __shared__ float sWm[8 * COUT];               // per-warp channel maxes
    __shared__ float sMax[COUT];

    int tid = threadIdx.x;
    for (int k = tid; k < N_GROUPS * CIN * COUT / 4; k += 256)
        ((float4*)sW)[k] = ((const float4*)W)[k];
    for (int k = tid; k < N_GROUPS * COUT; k += 256) {
        sSc[k] = g_scale[k];
        sSh[k] = g_shift[k];
    }
    __syncthreads();

    int p    = tid >> 3;
    int c0   = (tid & 7) << 3;
    int warp = tid >> 5, lane = tid & 31;

    for (int n = blockIdx.x; n < N; n += gridDim.x) {
        if (tid < 80)
            ((float4*)sIn)[tid] = ((const float4*)(in + (size_t)n * (NPTS * CIN)))[tid];
        int g = group_id(num[n]);
        __syncthreads();

        float v[CIN];
        #pragma unroll
        for (int i = 0; i < CIN; i++) v[i] = sIn[p * CIN + i];

        float acc[8];
        #pragma unroll
        for (int j = 0; j < 8; j++) acc[j] = 0.f;

        const float* wp = sW + g * (CIN * COUT) + c0;
        #pragma unroll
        for (int i = 0; i < CIN; i++) {
            float4 w0 = *(const float4*)(wp + i * COUT);
            float4 w1 = *(const float4*)(wp + i * COUT + 4);
            acc[0] += v[i] * w0.x; acc[1] += v[i] * w0.y;
            acc[2] += v[i] * w0.z; acc[3] += v[i] * w0.w;
            acc[4] += v[i] * w1.x; acc[5] += v[i] * w1.y;
            acc[6] += v[i] * w1.z; acc[7] += v[i] * w1.w;
        }

        float4 sc0 = *(const float4*)(sSc + g * COUT + c0);
        float4 sc1 = *(const float4*)(sSc + g * COUT + c0 + 4);
        float4 sh0 = *(const float4*)(sSh + g * COUT + c0);
        float4 sh1 = *(const float4*)(sSh + g * COUT + c0 + 4);

        float y[8];
        y[0] = fmaxf(acc[0] * sc0.x + sh0.x, 0.f);
        y[1] = fmaxf(acc[1] * sc0.y + sh0.y, 0.f);
        y[2] = fmaxf(acc[2] * sc0.z + sh0.z, 0.f);
        y[3] = fmaxf(acc[3] * sc0.w + sh0.w, 0.f);
        y[4] = fmaxf(acc[4] * sc1.x + sh1.x, 0.f);
        y[5] = fmaxf(acc[5] * sc1.y + sh1.y, 0.f);
        y[6] = fmaxf(acc[6] * sc1.z + sh1.z, 0.f);
        y[7] = fmaxf(acc[7] * sc1.w + sh1.w, 0.f);

        // write x half
        float* op = out + ((size_t)n * NPTS + p) * 128 + c0;
        *(float4*)op       = make_float4(y[0], y[1], y[2], y[3]);
        *(float4*)(op + 4) = make_float4(y[4], y[5], y[6], y[7]);

        // max over the 4 p's held by this warp (lanes differ by 8, 16)
        #pragma unroll
        for (int off = 8; off <= 16; off <<= 1) {
            #pragma unroll
            for (int j = 0; j < 8; j++)
                y[j] = fmaxf(y[j], __shfl_xor_sync(0xffffffffu, y[j], off));
        }
        if (lane < 8) {   // lane == tid&7 here, c0 matches
            float* wmp = sWm + warp * COUT + c0;
            *(float4*)wmp       = make_float4(y[0], y[1], y[2], y[3]);
            *(float4*)(wmp + 4) = make_float4(y[4], y[5], y[6], y[7]);
        }
        __syncthreads();

        if (tid < COUT) {
            float m = sWm[tid];
            #pragma unroll
            for (int ww = 1; ww < 8; ww++) m = fmaxf(m, sWm[ww * COUT + tid]);
            sMax[tid] = m;
        }
        __syncthreads();

        // write broadcast-max half
        float4 m0 = *(const float4*)(sMax + c0);
        float4 m1 = *(const float4*)(sMax + c0 + 4);
        *(float4*)(op + 64)     = m0;
        *(float4*)(op + 64 + 4) = m1;
    }
}

extern "C" void kernel_launch(void* const* d_in, const int* in_sizes, int n_in,
                              void* d_out, int out_size) {
    const float* inputs = (const float*)d_in[0];
    const int*   num    = (const int*)d_in[1];
    const float* W      = (const float*)d_in[2];
    const float* gamma  = (const float*)d_in[3];
    const float* beta   = (const float*)d_in[4];
    float* out = (float*)d_out;
    int N = in_sizes[1];   // num has one entry per voxel

    zero_kernel<<<1, 512>>>();
    stats_kernel<<<592, 256>>>(inputs, num, N);
    finalize_kernel<<<1, 320>>>(W, gamma, beta);
    main_kernel<<<1184, 256>>>(inputs, num, W, out, N);
}

// round 3
// speedup vs baseline: 2.4866x; 2.4866x over previous
#include <cuda_runtime.h>

#define N_GROUPS 5
#define CIN 10
#define NPTS 32
#define COUT 64
#define NACC 65          // 55 upper-tri second-moment entries + 10 first moments
#define BN_EPS 1e-3f

// global scratch (no allocations allowed)
__device__ float g_acc[N_GROUPS * NACC];
__device__ int   g_cnt[N_GROUPS];
__device__ float g_scale[N_GROUPS * COUT];
__device__ float g_shift[N_GROUPS * COUT];

__device__ __forceinline__ int group_id(int num) {
    if (num < 2) return 0;
    if (num < 3) return 1;
    if (num < 4) return 2;
    if (num < 16) return 3;
    return 4;
}

__global__ void zero_kernel() {
    int t = threadIdx.x;
    if (t < N_GROUPS * NACC) g_acc[t] = 0.f;
    if (t < N_GROUPS) g_cnt[t] = 0;
}

// ---------------------------------------------------------------------------
// Pass 1: per-group input moments.  S[g][i] = sum in_i ; M[g][i<=j] = sum in_i*in_j
// ---------------------------------------------------------------------------
__global__ void __launch_bounds__(256) stats_kernel(
    const float* __restrict__ in, const int* __restrict__ num, int N)
{
    __shared__ float sIn[8 * NPTS * CIN];        // 2560 floats staged coalesced
    __shared__ float sAcc[N_GROUPS * NACC];
    __shared__ int   sCnt[N_GROUPS];

    int tid = threadIdx.x;
    for (int k = tid; k < N_GROUPS * NACC; k += 256) sAcc[k] = 0.f;
    if (tid < N_GROUPS) sCnt[tid] = 0;

    int w = tid >> 5, lane = tid & 31;

    // entry -> (i,j) mapping for this lane (computed once)
    int i0, j0, i1, j1;
    {
        int e = lane, i = 0;
        while (e >= CIN - i) { e -= CIN - i; i++; }
        i0 = i; j0 = i + e;
    }
    {
        int e1 = lane + 32;
        if (e1 < 55) {
            int e = e1, i = 0;
            while (e >= CIN - i) { e -= CIN - i; i++; }
            i1 = i; j1 = i + e;
        } else {
            i1 = e1 - 55; j1 = -1;   // first-moment entry S[i1]
        }
    }
    __syncthreads();

    for (int n0 = blockIdx.x * 8; n0 < N; n0 += gridDim.x * 8) {
        int nv = min(8, N - n0);
        int nf4 = nv * (NPTS * CIN / 4);
        const float4* src = (const float4*)(in + (size_t)n0 * (NPTS * CIN));
        for (int k = tid; k < nf4; k += 256) ((float4*)sIn)[k] = src[k];
        __syncthreads();

        if (w < nv) {
            int n = n0 + w;
            int g = group_id(num[n]);
            const float* sv = sIn + w * (NPTS * CIN);
            float a0 = 0.f, a1 = 0.f, a2 = 0.f;
            #pragma unroll
            for (int p = 0; p < NPTS; p++) {
                const float* row = sv + p * CIN;
                a0 += row[i0] * row[j0];
                if (j1 >= 0) a1 += row[i1] * row[j1];
                else         a1 += row[i1];
                if (lane == 0) a2 += row[CIN - 1];   // entry 64 = S[9]
            }
            atomicAdd(&sAcc[g * NACC + lane], a0);
            atomicAdd(&sAcc[g * NACC + 32 + lane], a1);
            if (lane == 0) {
                atomicAdd(&sAcc[g * NACC + 64], a2);
                atomicAdd(&sCnt[g], 1);
            }
        }
        __syncthreads();
    }

    for (int k = tid; k < N_GROUPS * NACC; k += 256) atomicAdd(&g_acc[k], sAcc[k]);
    if (tid < N_GROUPS) atomicAdd(&g_cnt[tid], sCnt[tid]);
}

// ---------------------------------------------------------------------------
// Finalize: per (g,c): mean = (S.w)/cnt ; E[x^2] = w^T M w / cnt
// ---------------------------------------------------------------------------
__global__ void finalize_kernel(const float* __restrict__ W,
                                const float* __restrict__ gamma,
                                const float* __restrict__ beta)
{
    int t = threadIdx.x;
    if (t >= N_GROUPS * COUT) return;
    int g = t / COUT, c = t % COUT;
    float w[CIN];
    #pragma unroll
    for (int i = 0; i < CIN; i++) w[i] = W[(g * CIN + i) * COUT + c];

    const float* acc = &g_acc[g * NACC];
    float sum = 0.f;
    #pragma unroll
    for (int i = 0; i < CIN; i++) sum += acc[55 + i] * w[i];

    float sq = 0.f;
    int k = 0;
    #pragma unroll
    for (int i = 0; i < CIN; i++) {
        #pragma unroll 10
        for (int j = i; j < CIN; j++) {
            float term = acc[k++] * w[i] * w[j];
            sq += (i == j) ? term : 2.f * term;
        }
    }
    float denom = fmaxf((float)g_cnt[g] * (float)NPTS, 1.f);
    float mean = sum / denom;
    float var  = sq / denom - mean * mean;
    float scale = gamma[t] * rsqrtf(var + BN_EPS);
    g_scale[t] = scale;
    g_shift[t] = beta[t] - mean * scale;
}

// ---------------------------------------------------------------------------
// Pass 2: one WARP per voxel, weights in registers.
// half = lane>>4 selects point parity; c0 = (lane&15)*4 selects 4 channels.
// Per iteration the warp covers 2 points x 64 channels. Channel max is
// accumulated per-lane over 16 points, then combined with the peer lane
// (lane^16, same channels, other parity) via one shfl.xor per component.
// relu makes y >= 0, so mx init 0 is exact. No block syncs in voxel loop.
// ---------------------------------------------------------------------------
__global__ void __launch_bounds__(256) main_kernel(
    const float* __restrict__ in, const int* __restrict__ num,
    const float* __restrict__ W, float* __restrict__ out, int N)
{
    __shared__ float sW[N_GROUPS * CIN * COUT];   // 3200 floats
    __shared__ float sSc[N_GROUPS * COUT];
    __shared__ float sSh[N_GROUPS * COUT];
    __shared__ float sIn[8][NPTS * CIN];          // per-warp staging, 320 f each

    int tid = threadIdx.x;
    for (int k = tid; k < N_GROUPS * CIN * COUT / 4; k += 256)
        ((float4*)sW)[k] = ((const float4*)W)[k];
    for (int k = tid; k < N_GROUPS * COUT; k += 256) {
        sSc[k] = g_scale[k];
        sSh[k] = g_shift[k];
    }
    __syncthreads();

    int warp = tid >> 5, lane = tid & 31;
    int half = lane >> 4;            // 0 or 1: point parity
    int c0   = (lane & 15) << 2;     // 4 channels per lane
    float* sInW = sIn[warp];

    int warpGlobal = blockIdx.x * 8 + warp;
    int warpStride = gridDim.x * 8;

    for (int n = warpGlobal; n < N; n += warpStride) {
        // stage this voxel's input: 80 float4, coalesced, warp-private
        const float4* src = (const float4*)(in + (size_t)n * (NPTS * CIN));
        float4* dst = (float4*)sInW;
        dst[lane]      = src[lane];
        dst[lane + 32] = src[lane + 32];
        if (lane < 16) dst[lane + 64] = src[lane + 64];

        int g = group_id(__ldg(&num[n]));
        __syncwarp();

        // weights + affine into registers (once per voxel)
        float4 w[CIN];
        const float* wp = sW + g * (CIN * COUT) + c0;
        #pragma unroll
        for (int i = 0; i < CIN; i++) w[i] = *(const float4*)(wp + i * COUT);
        float4 sc = *(const float4*)(sSc + g * COUT + c0);
        float4 sh = *(const float4*)(sSh + g * COUT + c0);

        float4 mx = make_float4(0.f, 0.f, 0.f, 0.f);
        float* outv = out + (size_t)n * (NPTS * 128);

        #pragma unroll
        for (int p2 = 0; p2 < 16; p2++) {
            int p = p2 * 2 + half;
            const float* v = sInW + p * CIN;
            float a0 = 0.f, a1 = 0.f, a2 = 0.f, a3 = 0.f;
            #pragma unroll
            for (int i = 0; i < CIN; i++) {
                float vi = v[i];
                a0 += vi * w[i].x;
                a1 += vi * w[i].y;
                a2 += vi * w[i].z;
                a3 += vi * w[i].w;
            }
            float y0 = fmaxf(a0 * sc.x + sh.x, 0.f);
            float y1 = fmaxf(a1 * sc.y + sh.y, 0.f);
            float y2 = fmaxf(a2 * sc.z + sh.z, 0.f);
            float y3 = fmaxf(a3 * sc.w + sh.w, 0.f);
            mx.x = fmaxf(mx.x, y0);
            mx.y = fmaxf(mx.y, y1);
            mx.z = fmaxf(mx.z, y2);
            mx.w = fmaxf(mx.w, y3);
            *(float4*)(outv + p * 128 + c0) = make_float4(y0, y1, y2, y3);
        }

        // combine max with peer lane (same channels, other point parity)
        mx.x = fmaxf(mx.x, __shfl_xor_sync(0xffffffffu, mx.x, 16));
        mx.y = fmaxf(mx.y, __shfl_xor_sync(0xffffffffu, mx.y, 16));
        mx.z = fmaxf(mx.z, __shfl_xor_sync(0xffffffffu, mx.z, 16));
        mx.w = fmaxf(mx.w, __shfl_xor_sync(0xffffffffu, mx.w, 16));

        // broadcast-max half
        float* ob = outv + 64 + c0;
        #pragma unroll
        for (int p2 = 0; p2 < 16; p2++) {
            int p = p2 * 2 + half;
            *(float4*)(ob + p * 128) = mx;
        }
        __syncwarp();   // protect sInW before next iteration's staging
    }
}

extern "C" void kernel_launch(void* const* d_in, const int* in_sizes, int n_in,
                              void* d_out, int out_size) {
    const float* inputs = (const float*)d_in[0];
    const int*   num    = (const int*)d_in[1];
    const float* W      = (const float*)d_in[2];
    const float* gamma  = (const float*)d_in[3];
    const float* beta   = (const float*)d_in[4];
    float* out = (float*)d_out;
    int N = in_sizes[1];   // num has one entry per voxel

    zero_kernel<<<1, 512>>>();
    stats_kernel<<<1184, 256>>>(inputs, num, N);
    finalize_kernel<<<1, 320>>>(W, gamma, beta);
    main_kernel<<<1480, 256>>>(inputs, num, W, out, N);
}

// round 4
// speedup vs baseline: 2.6115x; 1.0502x over previous
#include <cuda_runtime.h>

#define N_GROUPS 5
#define CIN 10
#define NPTS 32
#define COUT 64
#define NACC 65          // 55 upper-tri second-moment entries + 10 first moments
#define BN_EPS 1e-3f

// global scratch (no allocations allowed)
__device__ float g_acc[N_GROUPS * NACC];
__device__ int   g_cnt[N_GROUPS];
__device__ float g_wf[N_GROUPS * CIN * COUT];   // scale-folded weights
__device__ float g_shift[N_GROUPS * COUT];

__device__ __forceinline__ int group_id(int num) {
    if (num < 2) return 0;
    if (num < 3) return 1;
    if (num < 4) return 2;
    if (num < 16) return 3;
    return 4;
}

__global__ void zero_kernel() {
    int t = threadIdx.x;
    if (t < N_GROUPS * NACC) g_acc[t] = 0.f;
    if (t < N_GROUPS) g_cnt[t] = 0;
}

// ---------------------------------------------------------------------------
// Pass 1: per-group input moments. Warp-private staging, no block syncs in
// the voxel loop. Lane k accumulates entries k and k+32; lane 0 also entry 64.
// ---------------------------------------------------------------------------
__global__ void __launch_bounds__(256) stats_kernel(
    const float* __restrict__ in, const int* __restrict__ num, int N)
{
    __shared__ float sIn[8][NPTS * CIN];         // per-warp staging
    __shared__ float sAcc[N_GROUPS * NACC];
    __shared__ int   sCnt[N_GROUPS];

    int tid = threadIdx.x;
    for (int k = tid; k < N_GROUPS * NACC; k += 256) sAcc[k] = 0.f;
    if (tid < N_GROUPS) sCnt[tid] = 0;

    int w = tid >> 5, lane = tid & 31;
    float* sInW = sIn[w];

    // entry -> (i,j) mapping for this lane (computed once)
    int i0, j0, i1, j1;
    {
        int e = lane, i = 0;
        while (e >= CIN - i) { e -= CIN - i; i++; }
        i0 = i; j0 = i + e;
    }
    {
        int e1 = lane + 32;
        if (e1 < 55) {
            int e = e1, i = 0;
            while (e >= CIN - i) { e -= CIN - i; i++; }
            i1 = i; j1 = i + e;
        } else {
            i1 = e1 - 55; j1 = -1;   // first-moment entry S[i1]
        }
    }
    __syncthreads();

    int warpGlobal = blockIdx.x * 8 + w;
    int warpStride = gridDim.x * 8;

    for (int n = warpGlobal; n < N; n += warpStride) {
        // stage voxel, warp-private, coalesced
        const float4* src = (const float4*)(in + (size_t)n * (NPTS * CIN));
        float4* dst = (float4*)sInW;
        dst[lane]      = src[lane];
        dst[lane + 32] = src[lane + 32];
        if (lane < 16) dst[lane + 64] = src[lane + 64];
        int g = group_id(__ldg(&num[n]));
        __syncwarp();

        float a0 = 0.f, a1 = 0.f, a2 = 0.f;
        #pragma unroll
        for (int p = 0; p < NPTS; p++) {
            const float* row = sInW + p * CIN;
            a0 += row[i0] * row[j0];
            if (j1 >= 0) a1 += row[i1] * row[j1];
            else         a1 += row[i1];
            if (lane == 0) a2 += row[CIN - 1];   // entry 64 = S[9]
        }
        atomicAdd(&sAcc[g * NACC + lane], a0);
        atomicAdd(&sAcc[g * NACC + 32 + lane], a1);
        if (lane == 0) {
            atomicAdd(&sAcc[g * NACC + 64], a2);
            atomicAdd(&sCnt[g], 1);
        }
        __syncwarp();
    }

    __syncthreads();
    for (int k = tid; k < N_GROUPS * NACC; k += 256) atomicAdd(&g_acc[k], sAcc[k]);
    if (tid < N_GROUPS) atomicAdd(&g_cnt[tid], sCnt[tid]);
}

// ---------------------------------------------------------------------------
// Finalize: per (g,c): mean = (S.w)/cnt ; E[x^2] = w^T M w / cnt
// Writes scale-folded weights g_wf = W * scale and shift.
// ---------------------------------------------------------------------------
__global__ void finalize_kernel(const float* __restrict__ W,
                                const float* __restrict__ gamma,
                                const float* __restrict__ beta)
{
    int t = threadIdx.x;
    if (t >= N_GROUPS * COUT) return;
    int g = t / COUT, c = t % COUT;
    float w[CIN];
    #pragma unroll
    for (int i = 0; i < CIN; i++) w[i] = W[(g * CIN + i) * COUT + c];

    const float* acc = &g_acc[g * NACC];
    float sum = 0.f;
    #pragma unroll
    for (int i = 0; i < CIN; i++) sum += acc[55 + i] * w[i];

    float sq = 0.f;
    int k = 0;
    #pragma unroll
    for (int i = 0; i < CIN; i++) {
        #pragma unroll 10
        for (int j = i; j < CIN; j++) {
            float term = acc[k++] * w[i] * w[j];
            sq += (i == j) ? term : 2.f * term;
        }
    }
    float denom = fmaxf((float)g_cnt[g] * (float)NPTS, 1.f);
    float mean = sum / denom;
    float var  = sq / denom - mean * mean;
    float scale = gamma[t] * rsqrtf(var + BN_EPS);
    g_shift[t] = beta[t] - mean * scale;
    #pragma unroll
    for (int i = 0; i < CIN; i++)
        g_wf[(g * CIN + i) * COUT + c] = w[i] * scale;
}

// ---------------------------------------------------------------------------
// Pass 2: one WARP per voxel, scale-folded weights in registers.
// 128-thread blocks, min 5 CTAs/SM for higher store-level parallelism.
// half = lane>>4 (point parity); c0 = (lane&15)*4 (4 channels per lane).
// ---------------------------------------------------------------------------
__global__ void __launch_bounds__(128, 5) main_kernel(
    const float* __restrict__ in, const int* __restrict__ num,
    float* __restrict__ out, int N)
{
    __shared__ float sW[N_GROUPS * CIN * COUT];   // 3200 floats (folded)
    __shared__ float sSh[N_GROUPS * COUT];
    __shared__ float sIn[4][NPTS * CIN];          // per-warp staging

    int tid = threadIdx.x;
    for (int k = tid; k < N_GROUPS * CIN * COUT / 4; k += 128)
        ((float4*)sW)[k] = ((const float4*)g_wf)[k];
    for (int k = tid; k < N_GROUPS * COUT; k += 128) sSh[k] = g_shift[k];
    __syncthreads();

    int warp = tid >> 5, lane = tid & 31;
    int half = lane >> 4;            // 0 or 1: point parity
    int c0   = (lane & 15) << 2;     // 4 channels per lane
    float* sInW = sIn[warp];

    int warpGlobal = blockIdx.x * 4 + warp;
    int warpStride = gridDim.x * 4;

    for (int n = warpGlobal; n < N; n += warpStride) {
        // stage this voxel's input: 80 float4, coalesced, warp-private
        const float4* src = (const float4*)(in + (size_t)n * (NPTS * CIN));
        float4* dst = (float4*)sInW;
        dst[lane]      = src[lane];
        dst[lane + 32] = src[lane + 32];
        if (lane < 16) dst[lane + 64] = src[lane + 64];

        int g = group_id(__ldg(&num[n]));
        __syncwarp();

        // folded weights + shift into registers (once per voxel)
        float4 w[CIN];
        const float* wp = sW + g * (CIN * COUT) + c0;
        #pragma unroll
        for (int i = 0; i < CIN; i++) w[i] = *(const float4*)(wp + i * COUT);
        float4 sh = *(const float4*)(sSh + g * COUT + c0);

        float4 mx = make_float4(0.f, 0.f, 0.f, 0.f);
        float* outv = out + (size_t)n * (NPTS * 128);

        #pragma unroll
        for (int p2 = 0; p2 < 16; p2++) {
            int p = p2 * 2 + half;
            const float* v = sInW + p * CIN;
            float a0 = sh.x, a1 = sh.y, a2 = sh.z, a3 = sh.w;
            #pragma unroll
            for (int i = 0; i < CIN; i++) {
                float vi = v[i];
                a0 += vi * w[i].x;
                a1 += vi * w[i].y;
                a2 += vi * w[i].z;
                a3 += vi * w[i].w;
            }
            float y0 = fmaxf(a0, 0.f);
            float y1 = fmaxf(a1, 0.f);
            float y2 = fmaxf(a2, 0.f);
            float y3 = fmaxf(a3, 0.f);
            mx.x = fmaxf(mx.x, y0);
            mx.y = fmaxf(mx.y, y1);
            mx.z = fmaxf(mx.z, y2);
            mx.w = fmaxf(mx.w, y3);
            *(float4*)(outv + p * 128 + c0) = make_float4(y0, y1, y2, y3);
        }

        // combine max with peer lane (same channels, other point parity)
        mx.x = fmaxf(mx.x, __shfl_xor_sync(0xffffffffu, mx.x, 16));
        mx.y = fmaxf(mx.y, __shfl_xor_sync(0xffffffffu, mx.y, 16));
        mx.z = fmaxf(mx.z, __shfl_xor_sync(0xffffffffu, mx.z, 16));
        mx.w = fmaxf(mx.w, __shfl_xor_sync(0xffffffffu, mx.w, 16));

        // broadcast-max half
        float* ob = outv + 64 + c0;
        #pragma unroll
        for (int p2 = 0; p2 < 16; p2++) {
            int p = p2 * 2 + half;
            *(float4*)(ob + p * 128) = mx;
        }
        __syncwarp();   // protect sInW before next iteration's staging
    }
}

extern "C" void kernel_launch(void* const* d_in, const int* in_sizes, int n_in,
                              void* d_out, int out_size) {
    const float* inputs = (const float*)d_in[0];
    const int*   num    = (const int*)d_in[1];
    const float* W      = (const float*)d_in[2];
    const float* gamma  = (const float*)d_in[3];
    const float* beta   = (const float*)d_in[4];
    float* out = (float*)d_out;
    int N = in_sizes[1];   // num has one entry per voxel

    zero_kernel<<<1, 512>>>();
    stats_kernel<<<1184, 256>>>(inputs, num, N);
    finalize_kernel<<<1, 320>>>(W, gamma, beta);
    main_kernel<<<2960, 128>>>(inputs, num, out, N);
}